// round 4
// baseline (speedup 1.0000x reference)
#include <cuda_runtime.h>
#include <cstdint>

// Problem constants
#define NTOK   32768
#define DIM    4096
#define NE     64
#define TM     128            // tokens per block
#define KC     32             // K chunk
#define NTHR   128
#define NCHUNK (DIM / KC)     // 128

// Output layout: [weights (NTOK*2) | indices as float (NTOK*2) | new_bias (NE)]
#define OFF_IDX  (NTOK * 2)
#define OFF_BIAS (NTOK * 4)

#define FLAG_CAP 8192
#define TAU      1e-3f        // near-tie threshold (abs); fp32 score noise ~2e-5

__device__ float g_expert_sums[NE];
__device__ int   g_flag_count;
__device__ int   g_flag_tokens[FLAG_CAP];

__device__ __forceinline__ unsigned long long pack2(float lo, float hi) {
    unsigned long long r;
    asm("mov.b64 %0, {%1, %2};" : "=l"(r) : "f"(lo), "f"(hi));
    return r;
}
__device__ __forceinline__ void ffma2(unsigned long long& d,
                                      unsigned long long a, unsigned long long b) {
    asm("fma.rn.f32x2 %0, %1, %2, %0;" : "+l"(d) : "l"(a), "l"(b));
}
__device__ __forceinline__ float lo32(unsigned long long v) {
    return __uint_as_float((unsigned)(v & 0xffffffffull));
}
__device__ __forceinline__ float hi32(unsigned long long v) {
    return __uint_as_float((unsigned)(v >> 32));
}

struct SmemMM {
    float xs[KC][TM];            // x tile, transposed: xs[k][token]      (16 KB)
    ulonglong2 wdv[KC][4][8];    // W duplicated {w,w}, granule-interleaved (16 KB)
};
union SmemU {
    SmemMM mm;
    float sc[TM][NE + 4];        // epilogue scores, padded rows (34 KB)
};

__global__ void __launch_bounds__(NTHR)
gate_kernel(const float* __restrict__ x, const float* __restrict__ w,
            const float* __restrict__ bias, float* __restrict__ out)
{
    __shared__ SmemU sm;
    __shared__ float s_bias[NE];
    __shared__ float s_esum[NE];

    const int tid  = threadIdx.x;
    const int tok0 = blockIdx.x * TM;
    const int tg   = tid >> 3;   // 0..15  token group (8 tokens)
    const int eg   = tid & 7;    // 0..7   expert group (8 experts)

    if (tid < NE) { s_bias[tid] = bias[tid]; s_esum[tid] = 0.f; }

    unsigned long long acc[4][8];
    #pragma unroll
    for (int p = 0; p < 4; p++)
        #pragma unroll
        for (int e = 0; e < 8; e++) acc[p][e] = 0ull;

    const float4* xg = reinterpret_cast<const float4*>(x + (size_t)(tok0 + tid) * DIM);
    const int we = tid >> 1;
    const int wh = tid & 1;
    const float4* wg = reinterpret_cast<const float4*>(w + (size_t)we * DIM + wh * 16);
    const int wj = we & 7, wegw = we >> 3, wgidx = wj >> 1, whalf = wj & 1;

    float4 xr[8];
    float4 wr[4];

    #pragma unroll
    for (int i = 0; i < 8; i++) xr[i] = xg[i];
    #pragma unroll
    for (int i = 0; i < 4; i++) wr[i] = wg[i];

    const float4* xgn = xg + (KC / 4);
    const float4* wgn = wg + (KC / 4);

    for (int kc = 0; kc < NCHUNK; kc++) {
        // ---- staged regs -> smem ----
        #pragma unroll
        for (int i = 0; i < 8; i++) {
            float4 v = xr[i];
            v.x = (v.x == v.x) ? v.x : 0.f;   // nan_to_num(x)
            v.y = (v.y == v.y) ? v.y : 0.f;
            v.z = (v.z == v.z) ? v.z : 0.f;
            v.w = (v.w == v.w) ? v.w : 0.f;
            sm.mm.xs[i * 4 + 0][tid] = v.x;
            sm.mm.xs[i * 4 + 1][tid] = v.y;
            sm.mm.xs[i * 4 + 2][tid] = v.z;
            sm.mm.xs[i * 4 + 3][tid] = v.w;
        }
        #pragma unroll
        for (int i = 0; i < 4; i++) {
            float4 v = wr[i];
            const int kb = wh * 16 + i * 4;
            reinterpret_cast<unsigned long long*>(&sm.mm.wdv[kb + 0][wgidx][wegw])[whalf] = pack2(v.x, v.x);
            reinterpret_cast<unsigned long long*>(&sm.mm.wdv[kb + 1][wgidx][wegw])[whalf] = pack2(v.y, v.y);
            reinterpret_cast<unsigned long long*>(&sm.mm.wdv[kb + 2][wgidx][wegw])[whalf] = pack2(v.z, v.z);
            reinterpret_cast<unsigned long long*>(&sm.mm.wdv[kb + 3][wgidx][wegw])[whalf] = pack2(v.w, v.w);
        }
        __syncthreads();

        // ---- prefetch next chunk ----
        if (kc + 1 < NCHUNK) {
            #pragma unroll
            for (int i = 0; i < 8; i++) xr[i] = xgn[i];
            #pragma unroll
            for (int i = 0; i < 4; i++) wr[i] = wgn[i];
            xgn += (KC / 4);
            wgn += (KC / 4);
        }

        // ---- compute chunk (f32x2 packed, fma-pipe bound) ----
        #pragma unroll
        for (int k = 0; k < KC; k++) {
            ulonglong2 xv0 = *reinterpret_cast<const ulonglong2*>(&sm.mm.xs[k][tg * 8]);
            ulonglong2 xv1 = *reinterpret_cast<const ulonglong2*>(&sm.mm.xs[k][tg * 8 + 4]);
            ulonglong2 w0 = sm.mm.wdv[k][0][eg];
            ulonglong2 w1 = sm.mm.wdv[k][1][eg];
            ulonglong2 w2 = sm.mm.wdv[k][2][eg];
            ulonglong2 w3 = sm.mm.wdv[k][3][eg];
            unsigned long long xp[4] = {xv0.x, xv0.y, xv1.x, xv1.y};
            unsigned long long wv[8] = {w0.x, w0.y, w1.x, w1.y, w2.x, w2.y, w3.x, w3.y};
            #pragma unroll
            for (int p = 0; p < 4; p++)
                #pragma unroll
                for (int e = 0; e < 8; e++)
                    ffma2(acc[p][e], xp[p], wv[e]);
        }
        __syncthreads();
    }

    // ---- epilogue: scores to smem ----
    #pragma unroll
    for (int p = 0; p < 4; p++) {
        const int t0 = tg * 8 + 2 * p;
        #pragma unroll
        for (int e = 0; e < 8; e++) {
            sm.sc[t0][eg * 8 + e]     = lo32(acc[p][e]);
            sm.sc[t0 + 1][eg * 8 + e] = hi32(acc[p][e]);
        }
    }
    __syncthreads();

    // ---- per-token top-3 + weights + near-tie flagging ----
    {
        const float* row = sm.sc[tid];
        float b1 = -3.4e38f, b2 = -3.4e38f, b3 = -3.4e38f;
        int i1 = 0, i2 = 0;
        #pragma unroll
        for (int e = 0; e < NE; e++) {
            float s = row[e] + s_bias[e];
            if (s > b1)      { b3 = b2; b2 = b1; i2 = i1; b1 = s; i1 = e; }
            else if (s > b2) { b3 = b2; b2 = s; i2 = e; }
            else if (s > b3) { b3 = s; }
        }
        float ex = expf(b2 - b1);
        float w1 = 1.f / (1.f + ex);
        float w2 = ex * w1;
        const int gt = tok0 + tid;
        out[2 * gt]               = w1;
        out[2 * gt + 1]           = w2;
        out[OFF_IDX + 2 * gt]     = (float)i1;
        out[OFF_IDX + 2 * gt + 1] = (float)i2;
        atomicAdd(&s_esum[i1], w1);
        atomicAdd(&s_esum[i2], w2);
        // near-tie: index decision within fp32 noise margin -> exact recompute
        if ((b1 - b2) < TAU || (b2 - b3) < TAU) {
            int slot = atomicAdd(&g_flag_count, 1);
            if (slot < FLAG_CAP) g_flag_tokens[slot] = gt;
        }
    }
    __syncthreads();
    if (tid < NE) atomicAdd(&g_expert_sums[tid], s_esum[tid]);
}

// ---- fp64 exact recompute for near-tie tokens ----
__global__ void __launch_bounds__(128)
fixup_kernel(const float* __restrict__ x, const float* __restrict__ w,
             const float* __restrict__ bias, float* __restrict__ out)
{
    __shared__ double sc[128];
    int cnt = g_flag_count;
    if (cnt > FLAG_CAP) cnt = FLAG_CAP;

    const int e = threadIdx.x & 63;   // expert
    const int h = threadIdx.x >> 6;   // K half (0/1)

    for (int t = blockIdx.x; t < cnt; t += gridDim.x) {
        const int tok = g_flag_tokens[t];
        const float4* xr = reinterpret_cast<const float4*>(x + (size_t)tok * DIM + h * (DIM / 2));
        const float4* wr = reinterpret_cast<const float4*>(w + (size_t)e * DIM + h * (DIM / 2));
        double s0 = 0.0, s1 = 0.0, s2 = 0.0, s3 = 0.0;
        #pragma unroll 4
        for (int i = 0; i < DIM / 8; i++) {   // 512 float4 pairs
            float4 a = xr[i];
            float4 b = wr[i];
            a.x = (a.x == a.x) ? a.x : 0.f;
            a.y = (a.y == a.y) ? a.y : 0.f;
            a.z = (a.z == a.z) ? a.z : 0.f;
            a.w = (a.w == a.w) ? a.w : 0.f;
            s0 = fma((double)a.x, (double)b.x, s0);
            s1 = fma((double)a.y, (double)b.y, s1);
            s2 = fma((double)a.z, (double)b.z, s2);
            s3 = fma((double)a.w, (double)b.w, s3);
        }
        sc[threadIdx.x] = (s0 + s1) + (s2 + s3);
        __syncthreads();

        if (threadIdx.x == 0) {
            double b1 = -1e300, b2 = -1e300;
            int i1 = 0, i2 = 0;
            for (int ee = 0; ee < NE; ee++) {
                double v = sc[ee] + sc[ee + 64] + (double)bias[ee];
                if (v > b1)      { b2 = b1; i2 = i1; b1 = v; i1 = ee; }
                else if (v > b2) { b2 = v; i2 = ee; }
            }
            double ex = exp(b2 - b1);
            double w1 = 1.0 / (1.0 + ex);
            double w2 = 1.0 - w1;
            // undo old contributions, apply new
            float ow1 = out[2 * tok], ow2 = out[2 * tok + 1];
            int   oi1 = (int)out[OFF_IDX + 2 * tok];
            int   oi2 = (int)out[OFF_IDX + 2 * tok + 1];
            atomicAdd(&g_expert_sums[oi1], -ow1);
            atomicAdd(&g_expert_sums[oi2], -ow2);
            atomicAdd(&g_expert_sums[i1], (float)w1);
            atomicAdd(&g_expert_sums[i2], (float)w2);
            out[2 * tok]               = (float)w1;
            out[2 * tok + 1]           = (float)w2;
            out[OFF_IDX + 2 * tok]     = (float)i1;
            out[OFF_IDX + 2 * tok + 1] = (float)i2;
        }
        __syncthreads();
    }
}

__global__ void zero_sums_kernel() {
    g_expert_sums[threadIdx.x] = 0.f;
    if (threadIdx.x == 0) g_flag_count = 0;
}

__global__ void finalize_kernel(const float* __restrict__ bias,
                                const float* __restrict__ tdist,
                                float* __restrict__ out)
{
    __shared__ float red[2];
    const int tid = threadIdx.x;   // 0..63
    float v = g_expert_sums[tid];
    float t = v;
    #pragma unroll
    for (int o = 16; o > 0; o >>= 1) t += __shfl_down_sync(0xffffffffu, t, o);
    if ((tid & 31) == 0) red[tid >> 5] = t;
    __syncthreads();
    const float total = red[0] + red[1];
    out[OFF_BIAS + tid] = bias[tid] + 0.001f * (tdist[tid] * total - v) / total;
}

extern "C" void kernel_launch(void* const* d_in, const int* in_sizes, int n_in,
                              void* d_out, int out_size) {
    const float* x     = (const float*)d_in[0];   // [32768, 4096]
    const float* w     = (const float*)d_in[1];   // [64, 4096]
    const float* bias  = (const float*)d_in[2];   // [64]
    const float* tdist = (const float*)d_in[3];   // [64]
    float* out = (float*)d_out;

    zero_sums_kernel<<<1, NE>>>();
    gate_kernel<<<NTOK / TM, NTHR>>>(x, w, bias, out);
    fixup_kernel<<<256, 128>>>(x, w, bias, out);
    finalize_kernel<<<1, NE>>>(bias, tdist, out);
}

// round 5
// speedup vs baseline: 1.6394x; 1.6394x over previous
#include <cuda_runtime.h>
#include <cuda_bf16.h>
#include <cstdint>

// Problem constants
#define NTOK   32768
#define DIM    4096
#define NE     64
#define TM     128            // tokens per block
#define KC     32             // K chunk (fp32 elems)
#define NTHR   128
#define NCHUNK (DIM / KC)     // 128
#define PITCH  20             // smem row pitch in 32-bit words (16 data + 4 pad)

// Output layout: [weights (NTOK*2) | indices as float (NTOK*2) | new_bias (NE)]
#define OFF_IDX  (NTOK * 2)
#define OFF_BIAS (NTOK * 4)

#define FLAG_CAP 8192
#define TAU      1e-3f        // near-tie threshold; bf16-split score noise ~3e-5

__device__ float g_expert_sums[NE];
__device__ int   g_flag_count;
__device__ int   g_flag_tokens[FLAG_CAP];

struct SmemMM {
    uint32_t xs_hi[TM][PITCH];   // x hi tile, bf16x2 words: word j = k{2j,2j+1}
    uint32_t xs_lo[TM][PITCH];   // x residual tile
    uint32_t wt_hi[NE][PITCH];   // w hi tile
    uint32_t wt_lo[NE][PITCH];   // w residual tile
};
union SmemU {
    SmemMM mm;                   // 30.7 KB
    float sc[TM][NE + 4];        // epilogue scores, padded rows (34.8 KB)
};

__device__ __forceinline__ void mma_bf16(float* d, const uint32_t* a,
                                         uint32_t b0, uint32_t b1) {
    asm volatile(
        "mma.sync.aligned.m16n8k16.row.col.f32.bf16.bf16.f32 "
        "{%0,%1,%2,%3}, {%4,%5,%6,%7}, {%8,%9}, {%0,%1,%2,%3};"
        : "+f"(d[0]), "+f"(d[1]), "+f"(d[2]), "+f"(d[3])
        : "r"(a[0]), "r"(a[1]), "r"(a[2]), "r"(a[3]), "r"(b0), "r"(b1));
}

__device__ __forceinline__ float n2n(float v) { return (v == v) ? v : 0.f; }

// split a,b into bf16 hi (packed word) and bf16 residual (packed word)
__device__ __forceinline__ void split2(float a, float b, uint32_t& hi, uint32_t& lo) {
    __nv_bfloat16 ha = __float2bfloat16_rn(a);
    __nv_bfloat16 hb = __float2bfloat16_rn(b);
    float ra = a - __bfloat162float(ha);
    float rb = b - __bfloat162float(hb);
    __nv_bfloat16 la = __float2bfloat16_rn(ra);
    __nv_bfloat16 lb = __float2bfloat16_rn(rb);
    hi = (uint32_t)__bfloat16_as_ushort(ha) | ((uint32_t)__bfloat16_as_ushort(hb) << 16);
    lo = (uint32_t)__bfloat16_as_ushort(la) | ((uint32_t)__bfloat16_as_ushort(lb) << 16);
}

__global__ void __launch_bounds__(NTHR)
gate_kernel(const float* __restrict__ x, const float* __restrict__ w,
            const float* __restrict__ bias, float* __restrict__ out)
{
    __shared__ SmemU sm;
    __shared__ float s_bias[NE];
    __shared__ float s_esum[NE];

    const int tid  = threadIdx.x;
    const int tok0 = blockIdx.x * TM;
    const int warp = tid >> 5;
    const int lane = tid & 31;
    const int gid  = lane >> 2;   // 0..7
    const int tig  = lane & 3;    // 0..3

    if (tid < NE) { s_bias[tid] = bias[tid]; s_esum[tid] = 0.f; }

    float acc[2][8][4];
    #pragma unroll
    for (int mt = 0; mt < 2; mt++)
        #pragma unroll
        for (int nt = 0; nt < 8; nt++)
            #pragma unroll
            for (int r = 0; r < 4; r++) acc[mt][nt][r] = 0.f;

    // global load mapping (same as before: thread owns one token row; pair owns one expert)
    const float4* xg = reinterpret_cast<const float4*>(x + (size_t)(tok0 + tid) * DIM);
    const int we = tid >> 1;           // expert this thread loads
    const int wh = tid & 1;            // which 16-float half of the chunk
    const float4* wg = reinterpret_cast<const float4*>(w + (size_t)we * DIM + wh * 16);

    float4 xr[8];
    float4 wr[4];

    #pragma unroll
    for (int i = 0; i < 8; i++) xr[i] = xg[i];
    #pragma unroll
    for (int i = 0; i < 4; i++) wr[i] = wg[i];

    const float4* xgn = xg + (KC / 4);
    const float4* wgn = wg + (KC / 4);

    for (int kc = 0; kc < NCHUNK; kc++) {
        // ---- staged regs -> smem (convert fp32 -> bf16 hi/lo) ----
        #pragma unroll
        for (int i = 0; i < 8; i++) {
            float4 v = xr[i];
            uint32_t h0, l0, h1, l1;
            split2(n2n(v.x), n2n(v.y), h0, l0);
            split2(n2n(v.z), n2n(v.w), h1, l1);
            *reinterpret_cast<uint2*>(&sm.mm.xs_hi[tid][i * 2]) = make_uint2(h0, h1);
            *reinterpret_cast<uint2*>(&sm.mm.xs_lo[tid][i * 2]) = make_uint2(l0, l1);
        }
        #pragma unroll
        for (int i = 0; i < 4; i++) {
            float4 v = wr[i];
            uint32_t h0, l0, h1, l1;
            split2(v.x, v.y, h0, l0);
            split2(v.z, v.w, h1, l1);
            *reinterpret_cast<uint2*>(&sm.mm.wt_hi[we][wh * 8 + i * 2]) = make_uint2(h0, h1);
            *reinterpret_cast<uint2*>(&sm.mm.wt_lo[we][wh * 8 + i * 2]) = make_uint2(l0, l1);
        }
        __syncthreads();

        // ---- prefetch next chunk into regs ----
        if (kc + 1 < NCHUNK) {
            #pragma unroll
            for (int i = 0; i < 8; i++) xr[i] = xgn[i];
            #pragma unroll
            for (int i = 0; i < 4; i++) wr[i] = wgn[i];
            xgn += (KC / 4);
            wgn += (KC / 4);
        }

        // ---- compute: 2 k-steps of 16, bf16 mma, 3 passes ----
        #pragma unroll
        for (int ks = 0; ks < 2; ks++) {
            const int c0 = ks * 8 + tig;
            uint32_t ah[2][4], al[2][4];
            #pragma unroll
            for (int mt = 0; mt < 2; mt++) {
                const int r0 = warp * 32 + mt * 16 + gid;
                ah[mt][0] = sm.mm.xs_hi[r0][c0];
                ah[mt][1] = sm.mm.xs_hi[r0 + 8][c0];
                ah[mt][2] = sm.mm.xs_hi[r0][c0 + 4];
                ah[mt][3] = sm.mm.xs_hi[r0 + 8][c0 + 4];
                al[mt][0] = sm.mm.xs_lo[r0][c0];
                al[mt][1] = sm.mm.xs_lo[r0 + 8][c0];
                al[mt][2] = sm.mm.xs_lo[r0][c0 + 4];
                al[mt][3] = sm.mm.xs_lo[r0 + 8][c0 + 4];
            }
            #pragma unroll
            for (int nt = 0; nt < 8; nt++) {
                const int er = nt * 8 + gid;
                uint32_t bh0 = sm.mm.wt_hi[er][c0];
                uint32_t bh1 = sm.mm.wt_hi[er][c0 + 4];
                uint32_t bl0 = sm.mm.wt_lo[er][c0];
                uint32_t bl1 = sm.mm.wt_lo[er][c0 + 4];
                #pragma unroll
                for (int mt = 0; mt < 2; mt++) {
                    mma_bf16(acc[mt][nt], ah[mt], bh0, bh1);  // hi*hi
                    mma_bf16(acc[mt][nt], al[mt], bh0, bh1);  // lo*hi
                    mma_bf16(acc[mt][nt], ah[mt], bl0, bl1);  // hi*lo
                }
            }
        }
        __syncthreads();
    }

    // ---- epilogue: scores to smem ----
    #pragma unroll
    for (int mt = 0; mt < 2; mt++) {
        const int r0 = warp * 32 + mt * 16 + gid;
        #pragma unroll
        for (int nt = 0; nt < 8; nt++) {
            const int c = nt * 8 + 2 * tig;
            *reinterpret_cast<float2*>(&sm.sc[r0][c])     = make_float2(acc[mt][nt][0], acc[mt][nt][1]);
            *reinterpret_cast<float2*>(&sm.sc[r0 + 8][c]) = make_float2(acc[mt][nt][2], acc[mt][nt][3]);
        }
    }
    __syncthreads();

    // ---- per-token top-3 + weights + near-tie flagging ----
    {
        const float* row = sm.sc[tid];
        float b1 = -3.4e38f, b2 = -3.4e38f, b3 = -3.4e38f;
        int i1 = 0, i2 = 0;
        #pragma unroll
        for (int e = 0; e < NE; e++) {
            float s = row[e] + s_bias[e];
            if (s > b1)      { b3 = b2; b2 = b1; i2 = i1; b1 = s; i1 = e; }
            else if (s > b2) { b3 = b2; b2 = s; i2 = e; }
            else if (s > b3) { b3 = s; }
        }
        float ex = expf(b2 - b1);
        float w1 = 1.f / (1.f + ex);
        float w2 = ex * w1;
        const int gt = tok0 + tid;
        out[2 * gt]               = w1;
        out[2 * gt + 1]           = w2;
        out[OFF_IDX + 2 * gt]     = (float)i1;
        out[OFF_IDX + 2 * gt + 1] = (float)i2;
        atomicAdd(&s_esum[i1], w1);
        atomicAdd(&s_esum[i2], w2);
        // near-tie: index decision within split-bf16 noise margin -> exact recompute
        if ((b1 - b2) < TAU || (b2 - b3) < TAU) {
            int slot = atomicAdd(&g_flag_count, 1);
            if (slot < FLAG_CAP) g_flag_tokens[slot] = gt;
        }
    }
    __syncthreads();
    if (tid < NE) atomicAdd(&g_expert_sums[tid], s_esum[tid]);
}

// ---- fp64 exact recompute for near-tie tokens ----
__global__ void __launch_bounds__(128)
fixup_kernel(const float* __restrict__ x, const float* __restrict__ w,
             const float* __restrict__ bias, float* __restrict__ out)
{
    __shared__ double sc[128];
    int cnt = g_flag_count;
    if (cnt > FLAG_CAP) cnt = FLAG_CAP;

    const int e = threadIdx.x & 63;   // expert
    const int h = threadIdx.x >> 6;   // K half (0/1)

    for (int t = blockIdx.x; t < cnt; t += gridDim.x) {
        const int tok = g_flag_tokens[t];
        const float4* xr = reinterpret_cast<const float4*>(x + (size_t)tok * DIM + h * (DIM / 2));
        const float4* wr = reinterpret_cast<const float4*>(w + (size_t)e * DIM + h * (DIM / 2));
        double s0 = 0.0, s1 = 0.0, s2 = 0.0, s3 = 0.0;
        #pragma unroll 4
        for (int i = 0; i < DIM / 8; i++) {
            float4 a = xr[i];
            float4 b = wr[i];
            a.x = (a.x == a.x) ? a.x : 0.f;
            a.y = (a.y == a.y) ? a.y : 0.f;
            a.z = (a.z == a.z) ? a.z : 0.f;
            a.w = (a.w == a.w) ? a.w : 0.f;
            s0 = fma((double)a.x, (double)b.x, s0);
            s1 = fma((double)a.y, (double)b.y, s1);
            s2 = fma((double)a.z, (double)b.z, s2);
            s3 = fma((double)a.w, (double)b.w, s3);
        }
        sc[threadIdx.x] = (s0 + s1) + (s2 + s3);
        __syncthreads();

        if (threadIdx.x == 0) {
            double b1 = -1e300, b2 = -1e300;
            int i1 = 0, i2 = 0;
            for (int ee = 0; ee < NE; ee++) {
                double v = sc[ee] + sc[ee + 64] + (double)bias[ee];
                if (v > b1)      { b2 = b1; i2 = i1; b1 = v; i1 = ee; }
                else if (v > b2) { b2 = v; i2 = ee; }
            }
            double ex = exp(b2 - b1);
            double w1 = 1.0 / (1.0 + ex);
            double w2 = 1.0 - w1;
            float ow1 = out[2 * tok], ow2 = out[2 * tok + 1];
            int   oi1 = (int)out[OFF_IDX + 2 * tok];
            int   oi2 = (int)out[OFF_IDX + 2 * tok + 1];
            atomicAdd(&g_expert_sums[oi1], -ow1);
            atomicAdd(&g_expert_sums[oi2], -ow2);
            atomicAdd(&g_expert_sums[i1], (float)w1);
            atomicAdd(&g_expert_sums[i2], (float)w2);
            out[2 * tok]               = (float)w1;
            out[2 * tok + 1]           = (float)w2;
            out[OFF_IDX + 2 * tok]     = (float)i1;
            out[OFF_IDX + 2 * tok + 1] = (float)i2;
        }
        __syncthreads();
    }
}

__global__ void zero_sums_kernel() {
    g_expert_sums[threadIdx.x] = 0.f;
    if (threadIdx.x == 0) g_flag_count = 0;
}

__global__ void finalize_kernel(const float* __restrict__ bias,
                                const float* __restrict__ tdist,
                                float* __restrict__ out)
{
    __shared__ float red[2];
    const int tid = threadIdx.x;   // 0..63
    float v = g_expert_sums[tid];
    float t = v;
    #pragma unroll
    for (int o = 16; o > 0; o >>= 1) t += __shfl_down_sync(0xffffffffu, t, o);
    if ((tid & 31) == 0) red[tid >> 5] = t;
    __syncthreads();
    const float total = red[0] + red[1];
    out[OFF_BIAS + tid] = bias[tid] + 0.001f * (tdist[tid] * total - v) / total;
}

extern "C" void kernel_launch(void* const* d_in, const int* in_sizes, int n_in,
                              void* d_out, int out_size) {
    const float* x     = (const float*)d_in[0];   // [32768, 4096]
    const float* w     = (const float*)d_in[1];   // [64, 4096]
    const float* bias  = (const float*)d_in[2];   // [64]
    const float* tdist = (const float*)d_in[3];   // [64]
    float* out = (float*)d_out;

    zero_sums_kernel<<<1, NE>>>();
    gate_kernel<<<NTOK / TM, NTHR>>>(x, w, bias, out);
    fixup_kernel<<<256, 128>>>(x, w, bias, out);
    finalize_kernel<<<1, NE>>>(bias, tdist, out);
}